// round 16
// baseline (speedup 1.0000x reference)
#include <cuda_runtime.h>
#include <cuda_fp16.h>
#include <math.h>
#include <stdint.h>

#define BB      8192
#define IN_DIM  1024
#define MEM_DIM 1024
#define CTX_DIM 1024
#define NGATE   3072

// ---- fp16 GEMM tiling: BM=128 fixed, BN templated (128 or 64), 2 CTAs/SM ----
#define BM 128
#define BK 64
#define STG 3
#define A_TILE_B 18432            // 128 rows * 72 halfs * 2B (144B rows)
#define ZSPLIT 4

// ---------------------------------------------------------------------------
// Device scratch
// ---------------------------------------------------------------------------
__device__ __align__(256) float  g_part[ZSPLIT * NGATE * IN_DIM];
__device__ __align__(256) float  g_b1  [CTX_DIM];
__device__ __align__(256) float  g_b2  [CTX_DIM];
__device__ __align__(256) float  g_bgi [NGATE];
// fp16 operands / intermediates
__device__ __align__(256) __half g_inh [(size_t)BB * IN_DIM];
__device__ __align__(256) __half g_pvh [(size_t)BB * MEM_DIM];
__device__ __align__(256) __half g_fgwh[MEM_DIM * (MEM_DIM + IN_DIM)];
__device__ __align__(256) __half g_whhh[NGATE * MEM_DIM];
__device__ __align__(256) __half g_ogwh[MEM_DIM * MEM_DIM];
__device__ __align__(256) __half g_wgih[NGATE * IN_DIM];
__device__ __align__(256) __half g_gth [(size_t)BB * MEM_DIM];
__device__ __align__(256) __half g_udh [(size_t)BB * MEM_DIM];
__device__ __align__(256) __half g_gih [(size_t)BB * NGATE];
__device__ __align__(256) __half g_ghh [(size_t)BB * NGATE];
// fold-chain fp16 operands
__device__ __align__(256) __half g_iph [IN_DIM * CTX_DIM];
__device__ __align__(256) __half g_wvh [CTX_DIM * CTX_DIM];
__device__ __align__(256) __half g_oph [CTX_DIM * CTX_DIM];
__device__ __align__(256) __half g_wihh[NGATE * CTX_DIM];
__device__ __align__(256) __half g_m1h [IN_DIM * CTX_DIM];
__device__ __align__(256) __half g_m2h [IN_DIM * CTX_DIM];

// ---------------------------------------------------------------------------
// Helpers
// ---------------------------------------------------------------------------
__device__ __forceinline__ float sigmoidf_(float x) { return 1.0f / (1.0f + expf(-x)); }
__device__ __forceinline__ uint32_t pack2h(float a, float b) {
    __half2 h = __float22half2_rn(make_float2(a, b));
    return *(uint32_t*)&h;
}
__device__ __forceinline__ float4 up4(uint2 u) {
    float2 a = __half22float2(*(__half2*)&u.x);
    float2 b = __half22float2(*(__half2*)&u.y);
    return make_float4(a.x, a.y, b.x, b.y);
}

// ---------------------------------------------------------------------------
// Segmented fp16 mma.sync GEMM (f32 accum), multistage cp.async pipeline.
// Template NT = B nt-tiles per warp: NT=8 -> BN=128, NT=4 -> BN=64.
//   pre[m,n] = sum_seg sum_k A_seg[m,k]*B_seg[n,k]  (+bias[n])
//   mode 0: v = pre     mode 1: v = mul * sigmoid(pre)  (mul f32 or mulh f16)
//   C (f32, optional) and/or C2 (f16, optional) receive v.
// ---------------------------------------------------------------------------
struct Seg { const __half* A; int lda; const __half* B; int ldb; int K; };

template <int NT>
__global__ __launch_bounds__(256, 2)
void h16_gemm(Seg s0, Seg s1, Seg s2,
              const float* __restrict__ bias,
              const float* __restrict__ mul,
              const __half* __restrict__ mulh,
              float* __restrict__ C, __half* __restrict__ C2,
              int ldc, int mode, int partM)
{
    constexpr int BN      = NT * 16;                 // 128 or 64
    constexpr int B_TILE  = BN * 72 * 2;             // bytes
    constexpr int STAGE_B = A_TILE_B + B_TILE;
    constexpr int WNC     = NT * 8;                  // warp N extent

    extern __shared__ __half smh[];
    uint32_t sbase;
    asm("{ .reg .u64 t; cvta.to.shared.u64 t, %1; cvt.u32.u64 %0, t; }"
        : "=r"(sbase) : "l"(smh));

    const int tid = threadIdx.x;
    const int wid = tid >> 5, lid = tid & 31;
    const int g = lid >> 2, tg = lid & 3;
    const int wm = wid & 3, wn = wid >> 2;           // warps: 4(M) x 2(N)
    const int row0 = blockIdx.y * BM, col0 = blockIdx.x * BN;

    const int e0 = s0.K / BK;
    const int e1 = e0 + s1.K / BK;
    const int niter_tot = e1 + s2.K / BK;
    const int cnt = niter_tot / gridDim.z;
    const int it0 = blockIdx.z * cnt;
    const int it1 = it0 + cnt;

    if (C)  C  += (size_t)blockIdx.z * partM * ldc;
    if (C2) C2 += (size_t)blockIdx.z * partM * ldc;

    const __half* A0 = s0.A + (size_t)row0 * s0.lda;
    const __half* B0 = s0.B + (size_t)col0 * s0.ldb;
    const __half* A1 = s1.A ? s1.A + (size_t)row0 * s1.lda : A0;
    const __half* B1 = s1.B ? s1.B + (size_t)col0 * s1.ldb : B0;
    const __half* A2 = s2.A ? s2.A + (size_t)row0 * s2.lda : A0;
    const __half* B2 = s2.B ? s2.B + (size_t)col0 * s2.ldb : B0;

    // ldmatrix lane-derived byte offsets (row stride 144 B)
    const int lr  = lid & 7;
    const int s1b = (lid >> 3) & 1;
    const int cby = (lid >> 4) * 16;
    uint32_t offA[2], offB[NT / 2];
#pragma unroll
    for (int mt = 0; mt < 2; mt++)
        offA[mt] = (uint32_t)((wm * 32 + mt * 16 + lr + s1b * 8) * 144 + cby);
#pragma unroll
    for (int p = 0; p < NT / 2; p++)
        offB[p] = (uint32_t)((wn * WNC + p * 16 + lr + s1b * 8) * 144 + cby + A_TILE_B);

    auto load_stage = [&](int s, int kc) {
        const __half* Ag; const __half* Bg; int lda, ldb, k0;
        if (kc < e0)      { Ag = A0; Bg = B0; lda = s0.lda; ldb = s0.ldb; k0 = kc * BK; }
        else if (kc < e1) { Ag = A1; Bg = B1; lda = s1.lda; ldb = s1.ldb; k0 = (kc - e0) * BK; }
        else              { Ag = A2; Bg = B2; lda = s2.lda; ldb = s2.ldb; k0 = (kc - e1) * BK; }
        const uint32_t sa = sbase + (uint32_t)s * STAGE_B;
        const uint32_t sb = sa + A_TILE_B;
#pragma unroll
        for (int i = 0; i < 4; i++) {                 // A: 128 rows x 8 chunks
            int c = tid + i * 256, r = c >> 3, ch = c & 7;
            asm volatile("cp.async.cg.shared.global [%0], [%1], 16;"
                :: "r"(sa + (uint32_t)(r * 144 + ch * 16)),
                   "l"(Ag + (size_t)r * lda + k0 + ch * 8) : "memory");
        }
#pragma unroll
        for (int i = 0; i < BN / 32; i++) {           // B: BN rows x 8 chunks
            int c = tid + i * 256, r = c >> 3, ch = c & 7;
            asm volatile("cp.async.cg.shared.global [%0], [%1], 16;"
                :: "r"(sb + (uint32_t)(r * 144 + ch * 16)),
                   "l"(Bg + (size_t)r * ldb + k0 + ch * 8) : "memory");
        }
    };

    float acc[2][NT][4];
#pragma unroll
    for (int mt = 0; mt < 2; mt++)
#pragma unroll
        for (int nt = 0; nt < NT; nt++)
#pragma unroll
            for (int e = 0; e < 4; e++) acc[mt][nt][e] = 0.0f;

    for (int p = 0; p < STG - 1; p++) {
        load_stage(p, it0 + p);
        asm volatile("cp.async.commit_group;" ::: "memory");
    }

    for (int it = it0; it < it1; it++) {
        asm volatile("cp.async.wait_group %0;" :: "n"(STG - 2) : "memory");
        __syncthreads();

        const uint32_t base = sbase + (uint32_t)((it - it0) % STG) * STAGE_B;
#pragma unroll
        for (int ks = 0; ks < 4; ks++) {
            const uint32_t kbb = (uint32_t)ks * 32;
            uint32_t af[2][4], bf[NT][2];
#pragma unroll
            for (int mt = 0; mt < 2; mt++)
                asm volatile("ldmatrix.sync.aligned.m8n8.x4.shared.b16 {%0,%1,%2,%3}, [%4];"
                    : "=r"(af[mt][0]), "=r"(af[mt][1]), "=r"(af[mt][2]), "=r"(af[mt][3])
                    : "r"(base + offA[mt] + kbb));
#pragma unroll
            for (int p = 0; p < NT / 2; p++) {
                uint32_t q0, q1, q2, q3;
                asm volatile("ldmatrix.sync.aligned.m8n8.x4.shared.b16 {%0,%1,%2,%3}, [%4];"
                    : "=r"(q0), "=r"(q1), "=r"(q2), "=r"(q3)
                    : "r"(base + offB[p] + kbb));
                bf[2 * p][0] = q0; bf[2 * p + 1][0] = q1;
                bf[2 * p][1] = q2; bf[2 * p + 1][1] = q3;
            }
#pragma unroll
            for (int mt = 0; mt < 2; mt++)
#pragma unroll
                for (int nt = 0; nt < NT; nt++)
                    asm volatile(
                        "mma.sync.aligned.m16n8k16.row.col.f32.f16.f16.f32 "
                        "{%0,%1,%2,%3}, {%4,%5,%6,%7}, {%8,%9}, {%0,%1,%2,%3};"
                        : "+f"(acc[mt][nt][0]), "+f"(acc[mt][nt][1]),
                          "+f"(acc[mt][nt][2]), "+f"(acc[mt][nt][3])
                        : "r"(af[mt][0]), "r"(af[mt][1]), "r"(af[mt][2]), "r"(af[mt][3]),
                          "r"(bf[nt][0]), "r"(bf[nt][1]));
        }

        const int pre = it + STG - 1;
        if (pre < it1) load_stage((pre - it0) % STG, pre);
        asm volatile("cp.async.commit_group;" ::: "memory");
    }

    // ---- epilogue ----
#pragma unroll
    for (int mt = 0; mt < 2; mt++)
#pragma unroll
        for (int h = 0; h < 2; h++) {
            const int row = row0 + wm * 32 + mt * 16 + g + h * 8;
            const size_t rb = (size_t)row * ldc + col0 + wn * WNC;
            float*        crow  = C    ? C    + rb : nullptr;
            const float*  mrow  = mul  ? mul  + rb : nullptr;
            const __half* mhrow = mulh ? mulh + rb : nullptr;
            __half*       c2row = C2   ? C2   + rb : nullptr;
#pragma unroll
            for (int nt = 0; nt < NT; nt++) {
                const int col = nt * 8 + 2 * tg;
                float v0 = acc[mt][nt][h * 2 + 0];
                float v1 = acc[mt][nt][h * 2 + 1];
                if (bias) {
                    v0 += bias[col0 + wn * WNC + col];
                    v1 += bias[col0 + wn * WNC + col + 1];
                }
                if (mode == 1) {
                    float m0, m1;
                    if (mrow) { float2 m = *(const float2*)(mrow + col); m0 = m.x; m1 = m.y; }
                    else {
                        __half2 m = *(const __half2*)(mhrow + col);
                        float2 mf = __half22float2(m); m0 = mf.x; m1 = mf.y;
                    }
                    v0 = m0 * sigmoidf_(v0);
                    v1 = m1 * sigmoidf_(v1);
                }
                if (crow)  *(float2*)(crow + col) = make_float2(v0, v1);
                if (c2row) *(uint32_t*)(c2row + col) = pack2h(v0, v1);
            }
        }
}

// ---------------------------------------------------------------------------
// Small kernels
// ---------------------------------------------------------------------------
__global__ void transpose_h_kernel(const float* __restrict__ src, __half* __restrict__ dst,
                                   int R, int C)
{
    __shared__ float t[32][33];
    int bx = blockIdx.x * 32, by = blockIdx.y * 32;
#pragma unroll
    for (int j = 0; j < 32; j += 8)
        t[threadIdx.y + j][threadIdx.x] = src[(size_t)(by + threadIdx.y + j) * C + bx + threadIdx.x];
    __syncthreads();
#pragma unroll
    for (int j = 0; j < 32; j += 8)
        dst[(size_t)(bx + threadIdx.y + j) * R + by + threadIdx.x] =
            __float2half_rn(t[threadIdx.x][threadIdx.y + j]);
}

__global__ void f2h_kernel(const float4* __restrict__ x, uint4* __restrict__ y, int n8)
{
    int i = blockIdx.x * 256 + threadIdx.x;
    if (i >= n8) return;
    float4 v0 = x[2 * i], v1 = x[2 * i + 1];
    uint4 o;
    o.x = pack2h(v0.x, v0.y);
    o.y = pack2h(v0.z, v0.w);
    o.z = pack2h(v1.x, v1.y);
    o.w = pack2h(v1.z, v1.w);
    y[i] = o;
}

__global__ void reduce_zh_kernel(const float4* __restrict__ part, uint2* __restrict__ dst,
                                 int n4, int Z, int s4)
{
    int i = blockIdx.x * 256 + threadIdx.x;
    if (i >= n4) return;
    float4 a = part[i];
    for (int z = 1; z < Z; z++) {
        float4 v = part[i + z * s4];
        a.x += v.x; a.y += v.y; a.z += v.z; a.w += v.w;
    }
    uint2 o;
    o.x = pack2h(a.x, a.y);
    o.y = pack2h(a.z, a.w);
    dst[i] = o;
}

__global__ void gemv_kernel(const float* __restrict__ W, int ldw,
                            const float* __restrict__ x, const float* __restrict__ b,
                            float* __restrict__ y, int N, int K)
{
    int row = blockIdx.x * 8 + (threadIdx.x >> 5);
    int lane = threadIdx.x & 31;
    if (row >= N) return;
    float s = 0.0f;
    for (int k = lane; k < K; k += 32) s += W[(size_t)row * ldw + k] * x[k];
#pragma unroll
    for (int o = 16; o > 0; o >>= 1) s += __shfl_down_sync(0xFFFFFFFFu, s, o);
    if (lane == 0) y[row] = s + (b ? b[row] : 0.0f);
}

// GRU elementwise: all inputs fp16, output udh fp16 only
__global__ void ew_gru_kernel(const uint2* __restrict__ gih,
                              const uint2* __restrict__ ghh,
                              const uint2* __restrict__ gth,
                              uint2* __restrict__ updh, int n4)
{
    int i = blockIdx.x * 256 + threadIdx.x;
    if (i >= n4) return;
    const int M4 = MEM_DIM / 4;
    int b = i / M4, j = i - b * M4;
    size_t base = (size_t)b * (NGATE / 4);
    float4 gir = up4(gih[base + j]),          ghr = up4(ghh[base + j]);
    float4 giz = up4(gih[base + M4 + j]),     ghz = up4(ghh[base + M4 + j]);
    float4 gin = up4(gih[base + 2 * M4 + j]), ghn = up4(ghh[base + 2 * M4 + j]);
    float4 gd = up4(gth[i]);
    float4 u;
    {
        float r = sigmoidf_(gir.x + ghr.x), z = sigmoidf_(giz.x + ghz.x);
        u.x = (1.0f - z) * tanhf(gin.x + r * ghn.x) + z * gd.x;
    }
    {
        float r = sigmoidf_(gir.y + ghr.y), z = sigmoidf_(giz.y + ghz.y);
        u.y = (1.0f - z) * tanhf(gin.y + r * ghn.y) + z * gd.y;
    }
    {
        float r = sigmoidf_(gir.z + ghr.z), z = sigmoidf_(giz.z + ghz.z);
        u.z = (1.0f - z) * tanhf(gin.z + r * ghn.z) + z * gd.z;
    }
    {
        float r = sigmoidf_(gir.w + ghr.w), z = sigmoidf_(giz.w + ghz.w);
        u.w = (1.0f - z) * tanhf(gin.w + r * ghn.w) + z * gd.w;
    }
    uint2 o;
    o.x = pack2h(u.x, u.y);
    o.y = pack2h(u.z, u.w);
    updh[i] = o;
}

__global__ void fill_ones_kernel(float* __restrict__ out, int n)
{
    int idx = blockIdx.x * blockDim.x + threadIdx.x;
    if (idx < n) out[idx] = 1.0f;
}

// ---------------------------------------------------------------------------
// Launch
// ---------------------------------------------------------------------------
extern "C" void kernel_launch(void* const* d_in, const int* in_sizes, int n_in,
                              void* d_out, int out_size)
{
    const float* input      = (const float*)d_in[0];
    const float* prev       = (const float*)d_in[1];
    const float* in_proj_w  = (const float*)d_in[2];
    const float* in_proj_b  = (const float*)d_in[3];
    const float* out_proj_w = (const float*)d_in[4];
    const float* out_proj_b = (const float*)d_in[5];
    const float* ip_w       = (const float*)d_in[6];
    const float* ip_b       = (const float*)d_in[7];
    // d_in[8..9] mp_w/mp_b dead: softmax over a single key == 1
    const float* fg_w       = (const float*)d_in[10];
    const float* fg_b       = (const float*)d_in[11];
    const float* og_w       = (const float*)d_in[12];
    const float* og_b       = (const float*)d_in[13];
    const float* w_ih       = (const float*)d_in[14];
    const float* b_ih       = (const float*)d_in[15];
    const float* w_hh       = (const float*)d_in[16];
    const float* b_hh       = (const float*)d_in[17];
    float* out = (float*)d_out;

    const float* wv = in_proj_w + 2 * CTX_DIM * CTX_DIM;
    const float* bv = in_proj_b + 2 * CTX_DIM;

    float *part, *b1, *b2, *bgi;
    __half *inh, *pvh, *fgwh, *whhh, *ogwh, *wgih, *gth, *udh, *gih, *ghh;
    __half *iph, *wvh, *oph, *wihh, *m1h, *m2h;
    cudaGetSymbolAddress((void**)&part, g_part);
    cudaGetSymbolAddress((void**)&b1,   g_b1);
    cudaGetSymbolAddress((void**)&b2,   g_b2);
    cudaGetSymbolAddress((void**)&bgi,  g_bgi);
    cudaGetSymbolAddress((void**)&inh,  g_inh);
    cudaGetSymbolAddress((void**)&pvh,  g_pvh);
    cudaGetSymbolAddress((void**)&fgwh, g_fgwh);
    cudaGetSymbolAddress((void**)&whhh, g_whhh);
    cudaGetSymbolAddress((void**)&ogwh, g_ogwh);
    cudaGetSymbolAddress((void**)&wgih, g_wgih);
    cudaGetSymbolAddress((void**)&gth,  g_gth);
    cudaGetSymbolAddress((void**)&udh,  g_udh);
    cudaGetSymbolAddress((void**)&gih,  g_gih);
    cudaGetSymbolAddress((void**)&ghh,  g_ghh);
    cudaGetSymbolAddress((void**)&iph,  g_iph);
    cudaGetSymbolAddress((void**)&wvh,  g_wvh);
    cudaGetSymbolAddress((void**)&oph,  g_oph);
    cudaGetSymbolAddress((void**)&wihh, g_wihh);
    cudaGetSymbolAddress((void**)&m1h,  g_m1h);
    cudaGetSymbolAddress((void**)&m2h,  g_m2h);

    const int SMEM8 = STG * (A_TILE_B + 128 * 72 * 2);   // 110592
    const int SMEM4 = STG * (A_TILE_B + 64 * 72 * 2);    // 82944
    cudaFuncSetAttribute(h16_gemm<8>, cudaFuncAttributeMaxDynamicSharedMemorySize, SMEM8);
    cudaFuncSetAttribute(h16_gemm<4>, cudaFuncAttributeMaxDynamicSharedMemorySize, SMEM4);

    const Seg Z = {nullptr, 0, nullptr, 0, 0};
    const int NSQ = CTX_DIM * CTX_DIM;

    // launches #0-2: staging needed by FG
    f2h_kernel<<<(BB * IN_DIM / 8) / 256, 256>>>((const float4*)input, (uint4*)inh, BB * IN_DIM / 8);
    f2h_kernel<<<(BB * MEM_DIM / 8) / 256, 256>>>((const float4*)prev, (uint4*)pvh, BB * MEM_DIM / 8);
    f2h_kernel<<<(MEM_DIM * (MEM_DIM + IN_DIM) / 8) / 256, 256>>>(
        (const float4*)fg_w, (uint4*)fgwh, MEM_DIM * (MEM_DIM + IN_DIM) / 8);

    // launch #3 (ncu capture target): FG GEMM, BN=64
    // gth = rn16(rn16(prev) * sigmoid(prev@fgA^T + input@fgB^T + fg_b))
    {
        Seg a = {pvh, MEM_DIM, fgwh,           MEM_DIM + IN_DIM, MEM_DIM};
        Seg b = {inh, IN_DIM,  fgwh + MEM_DIM, MEM_DIM + IN_DIM, IN_DIM};
        h16_gemm<4><<<dim3(MEM_DIM / 64, BB / BM), 256, SMEM4>>>(
            a, b, Z, fg_b, nullptr, pvh, nullptr, gth, MEM_DIM, 1, 0);
    }

    // remaining staging + bias folds
    f2h_kernel<<<(NGATE * MEM_DIM / 8) / 256, 256>>>((const float4*)w_hh, (uint4*)whhh, NGATE * MEM_DIM / 8);
    f2h_kernel<<<(MEM_DIM * MEM_DIM / 8) / 256, 256>>>((const float4*)og_w, (uint4*)ogwh, MEM_DIM * MEM_DIM / 8);
    gemv_kernel<<<CTX_DIM / 8, 256>>>(wv,         CTX_DIM, ip_b, bv,         b1, CTX_DIM, CTX_DIM);
    gemv_kernel<<<CTX_DIM / 8, 256>>>(out_proj_w, CTX_DIM, b1,   out_proj_b, b2, CTX_DIM, CTX_DIM);
    gemv_kernel<<<NGATE / 8, 256>>>(w_ih, CTX_DIM, b2, b_ih, bgi, NGATE, CTX_DIM);

    // GH (f16 out): ghh = rn16(gated @ w_hh^T + b_hh)   [BN=64, grid 3072]
    {
        Seg a = {gth, MEM_DIM, whhh, MEM_DIM, MEM_DIM};
        h16_gemm<4><<<dim3(NGATE / 64, BB / BM), 256, SMEM4>>>(
            a, Z, Z, b_hh, nullptr, nullptr, nullptr, ghh, NGATE, 0, 0);
    }

    // ---- weight folds: single-pass fp16, split-K Z=4, f16 intermediates ----
    transpose_h_kernel<<<dim3(IN_DIM / 32, CTX_DIM / 32), dim3(32, 8)>>>(ip_w, iph, CTX_DIM, IN_DIM);
    f2h_kernel<<<(NSQ / 8) / 256, 256>>>((const float4*)wv, (uint4*)wvh, NSQ / 8);
    {   // M1T[IN,CTX] = ip_w^T @ wv^T
        Seg a = {iph, CTX_DIM, wvh, CTX_DIM, CTX_DIM};
        h16_gemm<8><<<dim3(CTX_DIM / 128, IN_DIM / BM, ZSPLIT), 256, SMEM8>>>(
            a, Z, Z, nullptr, nullptr, nullptr, part, nullptr, CTX_DIM, 0, IN_DIM);
        reduce_zh_kernel<<<(NSQ / 4) / 256, 256>>>(
            (const float4*)part, (uint2*)m1h, NSQ / 4, ZSPLIT, NSQ / 4);
    }
    f2h_kernel<<<(NSQ / 8) / 256, 256>>>((const float4*)out_proj_w, (uint4*)oph, NSQ / 8);
    {   // M2T[IN,CTX] = M1T @ out_proj_w^T
        Seg a = {m1h, CTX_DIM, oph, CTX_DIM, CTX_DIM};
        h16_gemm<8><<<dim3(CTX_DIM / 128, IN_DIM / BM, ZSPLIT), 256, SMEM8>>>(
            a, Z, Z, nullptr, nullptr, nullptr, part, nullptr, CTX_DIM, 0, IN_DIM);
        reduce_zh_kernel<<<(NSQ / 4) / 256, 256>>>(
            (const float4*)part, (uint2*)m2h, NSQ / 4, ZSPLIT, NSQ / 4);
    }
    f2h_kernel<<<(NGATE * CTX_DIM / 8) / 256, 256>>>((const float4*)w_ih, (uint4*)wihh, NGATE * CTX_DIM / 8);
    {   // WGIH[NGATE,IN] = rn16(w_ih @ M2T^T)
        Seg a = {wihh, CTX_DIM, m2h, CTX_DIM, CTX_DIM};
        h16_gemm<8><<<dim3(IN_DIM / 128, NGATE / BM, ZSPLIT), 256, SMEM8>>>(
            a, Z, Z, nullptr, nullptr, nullptr, part, nullptr, IN_DIM, 0, NGATE);
        reduce_zh_kernel<<<(NGATE * IN_DIM / 4) / 256, 256>>>(
            (const float4*)part, (uint2*)wgih, NGATE * IN_DIM / 4, ZSPLIT, NGATE * IN_DIM / 4);
    }

    // GI (f16 out): gih = rn16(input @ WGI^T + bgi)   [BN=64, grid 3072]
    {
        Seg a = {inh, IN_DIM, wgih, IN_DIM, IN_DIM};
        h16_gemm<4><<<dim3(NGATE / 64, BB / BM), 256, SMEM4>>>(
            a, Z, Z, bgi, nullptr, nullptr, nullptr, gih, NGATE, 0, 0);
    }
    // GRU elementwise -> udh (f16)
    ew_gru_kernel<<<(BB * MEM_DIM / 4) / 256, 256>>>(
        (const uint2*)gih, (const uint2*)ghh, (const uint2*)gth,
        (uint2*)udh, BB * MEM_DIM / 4);
    // out = upd * sigmoid(upd @ og_w^T + og_b)   [BN=64, grid 1024]
    {
        Seg a = {udh, MEM_DIM, ogwh, MEM_DIM, MEM_DIM};
        h16_gemm<4><<<dim3(MEM_DIM / 64, BB / BM), 256, SMEM4>>>(
            a, Z, Z, og_b, nullptr, udh, out, nullptr, MEM_DIM, 1, 0);
    }
    // attention weights: softmax over single key == 1.0
    int tail = out_size - BB * MEM_DIM;
    if (tail > 0)
        fill_ones_kernel<<<(tail + 255) / 256, 256>>>(out + BB * MEM_DIM, tail);
}

// round 17
// speedup vs baseline: 1.0550x; 1.0550x over previous
#include <cuda_runtime.h>
#include <cuda_fp16.h>
#include <math.h>
#include <stdint.h>

#define BB      8192
#define IN_DIM  1024
#define MEM_DIM 1024
#define CTX_DIM 1024
#define NGATE   3072

// ---- fp16 GEMM tiling: BM=128 fixed, BN templated (128 or 64), 2 CTAs/SM ----
#define BM 128
#define BK 64
#define STG 3
#define A_TILE_B 18432            // 128 rows * 72 halfs * 2B (144B rows)
#define ZSPLIT 4

// ---------------------------------------------------------------------------
// Device scratch
// ---------------------------------------------------------------------------
__device__ __align__(256) float  g_part[ZSPLIT * NGATE * IN_DIM];
__device__ __align__(256) float  g_b1  [CTX_DIM];
__device__ __align__(256) float  g_b2  [CTX_DIM];
__device__ __align__(256) float  g_bgi [NGATE];
// fp16 operands / intermediates
__device__ __align__(256) __half g_inh [(size_t)BB * IN_DIM];
__device__ __align__(256) __half g_pvh [(size_t)BB * MEM_DIM];
__device__ __align__(256) __half g_fgwh[MEM_DIM * (MEM_DIM + IN_DIM)];
__device__ __align__(256) __half g_whhh[NGATE * MEM_DIM];
__device__ __align__(256) __half g_ogwh[MEM_DIM * MEM_DIM];
__device__ __align__(256) __half g_wgih[NGATE * IN_DIM];
__device__ __align__(256) __half g_gth [(size_t)BB * MEM_DIM];
__device__ __align__(256) __half g_udh [(size_t)BB * MEM_DIM];
__device__ __align__(256) __half g_gih [(size_t)BB * NGATE];
__device__ __align__(256) __half g_ghh [(size_t)BB * NGATE];
// fold-chain fp16 operands
__device__ __align__(256) __half g_iph [IN_DIM * CTX_DIM];
__device__ __align__(256) __half g_wvh [CTX_DIM * CTX_DIM];
__device__ __align__(256) __half g_oph [CTX_DIM * CTX_DIM];
__device__ __align__(256) __half g_wihh[NGATE * CTX_DIM];
__device__ __align__(256) __half g_m1h [IN_DIM * CTX_DIM];
__device__ __align__(256) __half g_m2h [IN_DIM * CTX_DIM];

// ---------------------------------------------------------------------------
// Helpers
// ---------------------------------------------------------------------------
__device__ __forceinline__ float sigmoidf_(float x) { return 1.0f / (1.0f + expf(-x)); }
__device__ __forceinline__ uint32_t pack2h(float a, float b) {
    __half2 h = __float22half2_rn(make_float2(a, b));
    return *(uint32_t*)&h;
}
__device__ __forceinline__ float4 up4(uint2 u) {
    float2 a = __half22float2(*(__half2*)&u.x);
    float2 b = __half22float2(*(__half2*)&u.y);
    return make_float4(a.x, a.y, b.x, b.y);
}

// ---------------------------------------------------------------------------
// Segmented fp16 mma.sync GEMM (f32 accum), multistage cp.async pipeline.
// Template NT = B nt-tiles per warp: NT=8 -> BN=128, NT=4 -> BN=64.
//   pre[m,n] = sum_seg sum_k A_seg[m,k]*B_seg[n,k]  (+bias[n])
//   mode 0: v = pre     mode 1: v = mul * sigmoid(pre)  (mul f32 or mulh f16)
//   C (f32, optional) and/or C2 (f16, optional) receive v.
// ---------------------------------------------------------------------------
struct Seg { const __half* A; int lda; const __half* B; int ldb; int K; };

template <int NT>
__global__ __launch_bounds__(256, 2)
void h16_gemm(Seg s0, Seg s1, Seg s2,
              const float* __restrict__ bias,
              const float* __restrict__ mul,
              const __half* __restrict__ mulh,
              float* __restrict__ C, __half* __restrict__ C2,
              int ldc, int mode, int partM)
{
    constexpr int BN      = NT * 16;                 // 128 or 64
    constexpr int B_TILE  = BN * 72 * 2;             // bytes
    constexpr int STAGE_B = A_TILE_B + B_TILE;
    constexpr int WNC     = NT * 8;                  // warp N extent

    extern __shared__ __half smh[];
    uint32_t sbase;
    asm("{ .reg .u64 t; cvta.to.shared.u64 t, %1; cvt.u32.u64 %0, t; }"
        : "=r"(sbase) : "l"(smh));

    const int tid = threadIdx.x;
    const int wid = tid >> 5, lid = tid & 31;
    const int g = lid >> 2, tg = lid & 3;
    const int wm = wid & 3, wn = wid >> 2;           // warps: 4(M) x 2(N)
    const int row0 = blockIdx.y * BM, col0 = blockIdx.x * BN;

    const int e0 = s0.K / BK;
    const int e1 = e0 + s1.K / BK;
    const int niter_tot = e1 + s2.K / BK;
    const int cnt = niter_tot / gridDim.z;
    const int it0 = blockIdx.z * cnt;
    const int it1 = it0 + cnt;

    if (C)  C  += (size_t)blockIdx.z * partM * ldc;
    if (C2) C2 += (size_t)blockIdx.z * partM * ldc;

    const __half* A0 = s0.A + (size_t)row0 * s0.lda;
    const __half* B0 = s0.B + (size_t)col0 * s0.ldb;
    const __half* A1 = s1.A ? s1.A + (size_t)row0 * s1.lda : A0;
    const __half* B1 = s1.B ? s1.B + (size_t)col0 * s1.ldb : B0;
    const __half* A2 = s2.A ? s2.A + (size_t)row0 * s2.lda : A0;
    const __half* B2 = s2.B ? s2.B + (size_t)col0 * s2.ldb : B0;

    // ldmatrix lane-derived byte offsets (row stride 144 B)
    const int lr  = lid & 7;
    const int s1b = (lid >> 3) & 1;
    const int cby = (lid >> 4) * 16;
    uint32_t offA[2], offB[NT / 2];
#pragma unroll
    for (int mt = 0; mt < 2; mt++)
        offA[mt] = (uint32_t)((wm * 32 + mt * 16 + lr + s1b * 8) * 144 + cby);
#pragma unroll
    for (int p = 0; p < NT / 2; p++)
        offB[p] = (uint32_t)((wn * WNC + p * 16 + lr + s1b * 8) * 144 + cby + A_TILE_B);

    auto load_stage = [&](int s, int kc) {
        const __half* Ag; const __half* Bg; int lda, ldb, k0;
        if (kc < e0)      { Ag = A0; Bg = B0; lda = s0.lda; ldb = s0.ldb; k0 = kc * BK; }
        else if (kc < e1) { Ag = A1; Bg = B1; lda = s1.lda; ldb = s1.ldb; k0 = (kc - e0) * BK; }
        else              { Ag = A2; Bg = B2; lda = s2.lda; ldb = s2.ldb; k0 = (kc - e1) * BK; }
        const uint32_t sa = sbase + (uint32_t)s * STAGE_B;
        const uint32_t sb = sa + A_TILE_B;
#pragma unroll
        for (int i = 0; i < 4; i++) {                 // A: 128 rows x 8 chunks
            int c = tid + i * 256, r = c >> 3, ch = c & 7;
            asm volatile("cp.async.cg.shared.global [%0], [%1], 16;"
                :: "r"(sa + (uint32_t)(r * 144 + ch * 16)),
                   "l"(Ag + (size_t)r * lda + k0 + ch * 8) : "memory");
        }
#pragma unroll
        for (int i = 0; i < BN / 32; i++) {           // B: BN rows x 8 chunks
            int c = tid + i * 256, r = c >> 3, ch = c & 7;
            asm volatile("cp.async.cg.shared.global [%0], [%1], 16;"
                :: "r"(sb + (uint32_t)(r * 144 + ch * 16)),
                   "l"(Bg + (size_t)r * ldb + k0 + ch * 8) : "memory");
        }
    };

    float acc[2][NT][4];
#pragma unroll
    for (int mt = 0; mt < 2; mt++)
#pragma unroll
        for (int nt = 0; nt < NT; nt++)
#pragma unroll
            for (int e = 0; e < 4; e++) acc[mt][nt][e] = 0.0f;

    for (int p = 0; p < STG - 1; p++) {
        load_stage(p, it0 + p);
        asm volatile("cp.async.commit_group;" ::: "memory");
    }

    for (int it = it0; it < it1; it++) {
        asm volatile("cp.async.wait_group %0;" :: "n"(STG - 2) : "memory");
        __syncthreads();

        const uint32_t base = sbase + (uint32_t)((it - it0) % STG) * STAGE_B;
#pragma unroll
        for (int ks = 0; ks < 4; ks++) {
            const uint32_t kbb = (uint32_t)ks * 32;
            uint32_t af[2][4], bf[NT][2];
#pragma unroll
            for (int mt = 0; mt < 2; mt++)
                asm volatile("ldmatrix.sync.aligned.m8n8.x4.shared.b16 {%0,%1,%2,%3}, [%4];"
                    : "=r"(af[mt][0]), "=r"(af[mt][1]), "=r"(af[mt][2]), "=r"(af[mt][3])
                    : "r"(base + offA[mt] + kbb));
#pragma unroll
            for (int p = 0; p < NT / 2; p++) {
                uint32_t q0, q1, q2, q3;
                asm volatile("ldmatrix.sync.aligned.m8n8.x4.shared.b16 {%0,%1,%2,%3}, [%4];"
                    : "=r"(q0), "=r"(q1), "=r"(q2), "=r"(q3)
                    : "r"(base + offB[p] + kbb));
                bf[2 * p][0] = q0; bf[2 * p + 1][0] = q1;
                bf[2 * p][1] = q2; bf[2 * p + 1][1] = q3;
            }
#pragma unroll
            for (int mt = 0; mt < 2; mt++)
#pragma unroll
                for (int nt = 0; nt < NT; nt++)
                    asm volatile(
                        "mma.sync.aligned.m16n8k16.row.col.f32.f16.f16.f32 "
                        "{%0,%1,%2,%3}, {%4,%5,%6,%7}, {%8,%9}, {%0,%1,%2,%3};"
                        : "+f"(acc[mt][nt][0]), "+f"(acc[mt][nt][1]),
                          "+f"(acc[mt][nt][2]), "+f"(acc[mt][nt][3])
                        : "r"(af[mt][0]), "r"(af[mt][1]), "r"(af[mt][2]), "r"(af[mt][3]),
                          "r"(bf[nt][0]), "r"(bf[nt][1]));
        }

        const int pre = it + STG - 1;
        if (pre < it1) load_stage((pre - it0) % STG, pre);
        asm volatile("cp.async.commit_group;" ::: "memory");
    }

    // ---- epilogue ----
#pragma unroll
    for (int mt = 0; mt < 2; mt++)
#pragma unroll
        for (int h = 0; h < 2; h++) {
            const int row = row0 + wm * 32 + mt * 16 + g + h * 8;
            const size_t rb = (size_t)row * ldc + col0 + wn * WNC;
            float*        crow  = C    ? C    + rb : nullptr;
            const float*  mrow  = mul  ? mul  + rb : nullptr;
            const __half* mhrow = mulh ? mulh + rb : nullptr;
            __half*       c2row = C2   ? C2   + rb : nullptr;
#pragma unroll
            for (int nt = 0; nt < NT; nt++) {
                const int col = nt * 8 + 2 * tg;
                float v0 = acc[mt][nt][h * 2 + 0];
                float v1 = acc[mt][nt][h * 2 + 1];
                if (bias) {
                    v0 += bias[col0 + wn * WNC + col];
                    v1 += bias[col0 + wn * WNC + col + 1];
                }
                if (mode == 1) {
                    float m0, m1;
                    if (mrow) { float2 m = *(const float2*)(mrow + col); m0 = m.x; m1 = m.y; }
                    else {
                        __half2 m = *(const __half2*)(mhrow + col);
                        float2 mf = __half22float2(m); m0 = mf.x; m1 = mf.y;
                    }
                    v0 = m0 * sigmoidf_(v0);
                    v1 = m1 * sigmoidf_(v1);
                }
                if (crow)  *(float2*)(crow + col) = make_float2(v0, v1);
                if (c2row) *(uint32_t*)(c2row + col) = pack2h(v0, v1);
            }
        }
}

// ---------------------------------------------------------------------------
// Small kernels
// ---------------------------------------------------------------------------
__global__ void transpose_h_kernel(const float* __restrict__ src, __half* __restrict__ dst,
                                   int R, int C)
{
    __shared__ float t[32][33];
    int bx = blockIdx.x * 32, by = blockIdx.y * 32;
#pragma unroll
    for (int j = 0; j < 32; j += 8)
        t[threadIdx.y + j][threadIdx.x] = src[(size_t)(by + threadIdx.y + j) * C + bx + threadIdx.x];
    __syncthreads();
#pragma unroll
    for (int j = 0; j < 32; j += 8)
        dst[(size_t)(bx + threadIdx.y + j) * R + by + threadIdx.x] =
            __float2half_rn(t[threadIdx.x][threadIdx.y + j]);
}

__global__ void f2h_kernel(const float4* __restrict__ x, uint4* __restrict__ y, int n8)
{
    int i = blockIdx.x * 256 + threadIdx.x;
    if (i >= n8) return;
    float4 v0 = x[2 * i], v1 = x[2 * i + 1];
    uint4 o;
    o.x = pack2h(v0.x, v0.y);
    o.y = pack2h(v0.z, v0.w);
    o.z = pack2h(v1.x, v1.y);
    o.w = pack2h(v1.z, v1.w);
    y[i] = o;
}

__global__ void reduce_zh_kernel(const float4* __restrict__ part, uint2* __restrict__ dst,
                                 int n4, int Z, int s4)
{
    int i = blockIdx.x * 256 + threadIdx.x;
    if (i >= n4) return;
    float4 a = part[i];
    for (int z = 1; z < Z; z++) {
        float4 v = part[i + z * s4];
        a.x += v.x; a.y += v.y; a.z += v.z; a.w += v.w;
    }
    uint2 o;
    o.x = pack2h(a.x, a.y);
    o.y = pack2h(a.z, a.w);
    dst[i] = o;
}

__global__ void gemv_kernel(const float* __restrict__ W, int ldw,
                            const float* __restrict__ x, const float* __restrict__ b,
                            float* __restrict__ y, int N, int K)
{
    int row = blockIdx.x * 8 + (threadIdx.x >> 5);
    int lane = threadIdx.x & 31;
    if (row >= N) return;
    float s = 0.0f;
    for (int k = lane; k < K; k += 32) s += W[(size_t)row * ldw + k] * x[k];
#pragma unroll
    for (int o = 16; o > 0; o >>= 1) s += __shfl_down_sync(0xFFFFFFFFu, s, o);
    if (lane == 0) y[row] = s + (b ? b[row] : 0.0f);
}

// GRU elementwise: all inputs fp16, output udh fp16 only
__global__ void ew_gru_kernel(const uint2* __restrict__ gih,
                              const uint2* __restrict__ ghh,
                              const uint2* __restrict__ gth,
                              uint2* __restrict__ updh, int n4)
{
    int i = blockIdx.x * 256 + threadIdx.x;
    if (i >= n4) return;
    const int M4 = MEM_DIM / 4;
    int b = i / M4, j = i - b * M4;
    size_t base = (size_t)b * (NGATE / 4);
    float4 gir = up4(gih[base + j]),          ghr = up4(ghh[base + j]);
    float4 giz = up4(gih[base + M4 + j]),     ghz = up4(ghh[base + M4 + j]);
    float4 gin = up4(gih[base + 2 * M4 + j]), ghn = up4(ghh[base + 2 * M4 + j]);
    float4 gd = up4(gth[i]);
    float4 u;
    {
        float r = sigmoidf_(gir.x + ghr.x), z = sigmoidf_(giz.x + ghz.x);
        u.x = (1.0f - z) * tanhf(gin.x + r * ghn.x) + z * gd.x;
    }
    {
        float r = sigmoidf_(gir.y + ghr.y), z = sigmoidf_(giz.y + ghz.y);
        u.y = (1.0f - z) * tanhf(gin.y + r * ghn.y) + z * gd.y;
    }
    {
        float r = sigmoidf_(gir.z + ghr.z), z = sigmoidf_(giz.z + ghz.z);
        u.z = (1.0f - z) * tanhf(gin.z + r * ghn.z) + z * gd.z;
    }
    {
        float r = sigmoidf_(gir.w + ghr.w), z = sigmoidf_(giz.w + ghz.w);
        u.w = (1.0f - z) * tanhf(gin.w + r * ghn.w) + z * gd.w;
    }
    uint2 o;
    o.x = pack2h(u.x, u.y);
    o.y = pack2h(u.z, u.w);
    updh[i] = o;
}

__global__ void fill_ones_kernel(float* __restrict__ out, int n)
{
    int idx = blockIdx.x * blockDim.x + threadIdx.x;
    if (idx < n) out[idx] = 1.0f;
}

// ---------------------------------------------------------------------------
// Launch
// ---------------------------------------------------------------------------
extern "C" void kernel_launch(void* const* d_in, const int* in_sizes, int n_in,
                              void* d_out, int out_size)
{
    const float* input      = (const float*)d_in[0];
    const float* prev       = (const float*)d_in[1];
    const float* in_proj_w  = (const float*)d_in[2];
    const float* in_proj_b  = (const float*)d_in[3];
    const float* out_proj_w = (const float*)d_in[4];
    const float* out_proj_b = (const float*)d_in[5];
    const float* ip_w       = (const float*)d_in[6];
    const float* ip_b       = (const float*)d_in[7];
    // d_in[8..9] mp_w/mp_b dead: softmax over a single key == 1
    const float* fg_w       = (const float*)d_in[10];
    const float* fg_b       = (const float*)d_in[11];
    const float* og_w       = (const float*)d_in[12];
    const float* og_b       = (const float*)d_in[13];
    const float* w_ih       = (const float*)d_in[14];
    const float* b_ih       = (const float*)d_in[15];
    const float* w_hh       = (const float*)d_in[16];
    const float* b_hh       = (const float*)d_in[17];
    float* out = (float*)d_out;

    const float* wv = in_proj_w + 2 * CTX_DIM * CTX_DIM;
    const float* bv = in_proj_b + 2 * CTX_DIM;

    float *part, *b1, *b2, *bgi;
    __half *inh, *pvh, *fgwh, *whhh, *ogwh, *wgih, *gth, *udh, *gih, *ghh;
    __half *iph, *wvh, *oph, *wihh, *m1h, *m2h;
    cudaGetSymbolAddress((void**)&part, g_part);
    cudaGetSymbolAddress((void**)&b1,   g_b1);
    cudaGetSymbolAddress((void**)&b2,   g_b2);
    cudaGetSymbolAddress((void**)&bgi,  g_bgi);
    cudaGetSymbolAddress((void**)&inh,  g_inh);
    cudaGetSymbolAddress((void**)&pvh,  g_pvh);
    cudaGetSymbolAddress((void**)&fgwh, g_fgwh);
    cudaGetSymbolAddress((void**)&whhh, g_whhh);
    cudaGetSymbolAddress((void**)&ogwh, g_ogwh);
    cudaGetSymbolAddress((void**)&wgih, g_wgih);
    cudaGetSymbolAddress((void**)&gth,  g_gth);
    cudaGetSymbolAddress((void**)&udh,  g_udh);
    cudaGetSymbolAddress((void**)&gih,  g_gih);
    cudaGetSymbolAddress((void**)&ghh,  g_ghh);
    cudaGetSymbolAddress((void**)&iph,  g_iph);
    cudaGetSymbolAddress((void**)&wvh,  g_wvh);
    cudaGetSymbolAddress((void**)&oph,  g_oph);
    cudaGetSymbolAddress((void**)&wihh, g_wihh);
    cudaGetSymbolAddress((void**)&m1h,  g_m1h);
    cudaGetSymbolAddress((void**)&m2h,  g_m2h);

    const int SMEM8 = STG * (A_TILE_B + 128 * 72 * 2);   // 110592
    const int SMEM4 = STG * (A_TILE_B + 64 * 72 * 2);    // 82944
    cudaFuncSetAttribute(h16_gemm<8>, cudaFuncAttributeMaxDynamicSharedMemorySize, SMEM8);
    cudaFuncSetAttribute(h16_gemm<4>, cudaFuncAttributeMaxDynamicSharedMemorySize, SMEM4);

    const Seg Z = {nullptr, 0, nullptr, 0, 0};
    const int NSQ = CTX_DIM * CTX_DIM;

    // launches #0-2: staging needed by FG
    f2h_kernel<<<(BB * IN_DIM / 8) / 256, 256>>>((const float4*)input, (uint4*)inh, BB * IN_DIM / 8);
    f2h_kernel<<<(BB * MEM_DIM / 8) / 256, 256>>>((const float4*)prev, (uint4*)pvh, BB * MEM_DIM / 8);
    f2h_kernel<<<(MEM_DIM * (MEM_DIM + IN_DIM) / 8) / 256, 256>>>(
        (const float4*)fg_w, (uint4*)fgwh, MEM_DIM * (MEM_DIM + IN_DIM) / 8);

    // launch #3 (ncu capture target): FG GEMM, BN=64 (grid 1024, wave-fit win)
    // gth = rn16(rn16(prev) * sigmoid(prev@fgA^T + input@fgB^T + fg_b))
    {
        Seg a = {pvh, MEM_DIM, fgwh,           MEM_DIM + IN_DIM, MEM_DIM};
        Seg b = {inh, IN_DIM,  fgwh + MEM_DIM, MEM_DIM + IN_DIM, IN_DIM};
        h16_gemm<4><<<dim3(MEM_DIM / 64, BB / BM), 256, SMEM4>>>(
            a, b, Z, fg_b, nullptr, pvh, nullptr, gth, MEM_DIM, 1, 0);
    }

    // remaining staging + bias folds
    f2h_kernel<<<(NGATE * MEM_DIM / 8) / 256, 256>>>((const float4*)w_hh, (uint4*)whhh, NGATE * MEM_DIM / 8);
    f2h_kernel<<<(MEM_DIM * MEM_DIM / 8) / 256, 256>>>((const float4*)og_w, (uint4*)ogwh, MEM_DIM * MEM_DIM / 8);
    gemv_kernel<<<CTX_DIM / 8, 256>>>(wv,         CTX_DIM, ip_b, bv,         b1, CTX_DIM, CTX_DIM);
    gemv_kernel<<<CTX_DIM / 8, 256>>>(out_proj_w, CTX_DIM, b1,   out_proj_b, b2, CTX_DIM, CTX_DIM);
    gemv_kernel<<<NGATE / 8, 256>>>(w_ih, CTX_DIM, b2, b_ih, bgi, NGATE, CTX_DIM);

    // GH (f16 out): ghh = rn16(gated @ w_hh^T + b_hh)   [BN=128, 5.2 waves]
    {
        Seg a = {gth, MEM_DIM, whhh, MEM_DIM, MEM_DIM};
        h16_gemm<8><<<dim3(NGATE / 128, BB / BM), 256, SMEM8>>>(
            a, Z, Z, b_hh, nullptr, nullptr, nullptr, ghh, NGATE, 0, 0);
    }

    // ---- weight folds: single-pass fp16, split-K Z=4, f16 intermediates ----
    transpose_h_kernel<<<dim3(IN_DIM / 32, CTX_DIM / 32), dim3(32, 8)>>>(ip_w, iph, CTX_DIM, IN_DIM);
    f2h_kernel<<<(NSQ / 8) / 256, 256>>>((const float4*)wv, (uint4*)wvh, NSQ / 8);
    {   // M1T[IN,CTX] = ip_w^T @ wv^T
        Seg a = {iph, CTX_DIM, wvh, CTX_DIM, CTX_DIM};
        h16_gemm<8><<<dim3(CTX_DIM / 128, IN_DIM / BM, ZSPLIT), 256, SMEM8>>>(
            a, Z, Z, nullptr, nullptr, nullptr, part, nullptr, CTX_DIM, 0, IN_DIM);
        reduce_zh_kernel<<<(NSQ / 4) / 256, 256>>>(
            (const float4*)part, (uint2*)m1h, NSQ / 4, ZSPLIT, NSQ / 4);
    }
    f2h_kernel<<<(NSQ / 8) / 256, 256>>>((const float4*)out_proj_w, (uint4*)oph, NSQ / 8);
    {   // M2T[IN,CTX] = M1T @ out_proj_w^T
        Seg a = {m1h, CTX_DIM, oph, CTX_DIM, CTX_DIM};
        h16_gemm<8><<<dim3(CTX_DIM / 128, IN_DIM / BM, ZSPLIT), 256, SMEM8>>>(
            a, Z, Z, nullptr, nullptr, nullptr, part, nullptr, CTX_DIM, 0, IN_DIM);
        reduce_zh_kernel<<<(NSQ / 4) / 256, 256>>>(
            (const float4*)part, (uint2*)m2h, NSQ / 4, ZSPLIT, NSQ / 4);
    }
    f2h_kernel<<<(NGATE * CTX_DIM / 8) / 256, 256>>>((const float4*)w_ih, (uint4*)wihh, NGATE * CTX_DIM / 8);
    {   // WGIH[NGATE,IN] = rn16(w_ih @ M2T^T)
        Seg a = {wihh, CTX_DIM, m2h, CTX_DIM, CTX_DIM};
        h16_gemm<8><<<dim3(IN_DIM / 128, NGATE / BM, ZSPLIT), 256, SMEM8>>>(
            a, Z, Z, nullptr, nullptr, nullptr, part, nullptr, IN_DIM, 0, NGATE);
        reduce_zh_kernel<<<(NGATE * IN_DIM / 4) / 256, 256>>>(
            (const float4*)part, (uint2*)wgih, NGATE * IN_DIM / 4, ZSPLIT, NGATE * IN_DIM / 4);
    }

    // GI (f16 out): gih = rn16(input @ WGI^T + bgi)   [BN=128, 5.2 waves]
    {
        Seg a = {inh, IN_DIM, wgih, IN_DIM, IN_DIM};
        h16_gemm<8><<<dim3(NGATE / 128, BB / BM), 256, SMEM8>>>(
            a, Z, Z, bgi, nullptr, nullptr, nullptr, gih, NGATE, 0, 0);
    }
    // GRU elementwise -> udh (f16)
    ew_gru_kernel<<<(BB * MEM_DIM / 4) / 256, 256>>>(
        (const uint2*)gih, (const uint2*)ghh, (const uint2*)gth,
        (uint2*)udh, BB * MEM_DIM / 4);
    // out = upd * sigmoid(upd @ og_w^T + og_b)   [BN=64, grid 1024]
    {
        Seg a = {udh, MEM_DIM, ogwh, MEM_DIM, MEM_DIM};
        h16_gemm<4><<<dim3(MEM_DIM / 64, BB / BM), 256, SMEM4>>>(
            a, Z, Z, og_b, nullptr, udh, out, nullptr, MEM_DIM, 1, 0);
    }
    // attention weights: softmax over single key == 1.0
    int tail = out_size - BB * MEM_DIM;
    if (tail > 0)
        fill_ones_kernel<<<(tail + 255) / 256, 256>>>(out + BB * MEM_DIM, tail);
}